// round 1
// baseline (speedup 1.0000x reference)
#include <cuda_runtime.h>
#include <math.h>

#define EPSV 1e-4f

// Scratch (no allocations allowed): P = W1@W2@W3 (57x2), a[b,t] symmetric 2x2 as 3 floats
__device__ float g_P[57 * 2];
__device__ float g_a[128 * 64 * 3];

// ---------------------------------------------------------------------------
// Kernel 1: P = W1 (57x20) @ W2 (20x10) @ W3 (10x2). One tiny block.
// ---------------------------------------------------------------------------
__global__ void compute_P_kernel(const float* __restrict__ W1,
                                 const float* __restrict__ W2,
                                 const float* __restrict__ W3) {
    __shared__ float W23[20 * 2];
    int tid = threadIdx.x;
    if (tid < 40) {
        int j = tid >> 1, u = tid & 1;
        float s = 0.f;
        #pragma unroll
        for (int k = 0; k < 10; k++) s += W2[j * 10 + k] * W3[k * 2 + u];
        W23[j * 2 + u] = s;
    }
    __syncthreads();
    if (tid < 114) {
        int i = tid >> 1, u = tid & 1;
        float s = 0.f;
        #pragma unroll
        for (int j = 0; j < 20; j++) s += W1[i * 20 + j] * W23[j * 2 + u];
        g_P[i * 2 + u] = s;
    }
}

// ---------------------------------------------------------------------------
// Kernel 2: a[bt] = P^T x[bt] P  (3 independent values since symmetric).
// One block per (b,t) matrix (8192 blocks). Coalesced streaming read of x,
// 5 FMA per element, block reduction. DRAM-bound by design (~106 MB read).
// ---------------------------------------------------------------------------
__global__ void __launch_bounds__(256, 8)
stage_a_kernel(const float* __restrict__ x) {
    __shared__ float p0[57], p1[57];
    __shared__ float red0[8], red1[8], red2[8];
    int tid = threadIdx.x;
    if (tid < 57) { p0[tid] = g_P[tid * 2]; p1[tid] = g_P[tid * 2 + 1]; }
    __syncthreads();

    const float* xm = x + (size_t)blockIdx.x * 3249;  // 57*57
    float c00 = 0.f, c01 = 0.f, c11 = 0.f;
    for (int idx = tid; idx < 3249; idx += 256) {
        float xv = xm[idx];
        int i = idx / 57;
        int k = idx - i * 57;
        float t0 = p0[i] * xv;
        float t1 = p1[i] * xv;
        c00 = fmaf(t0, p0[k], c00);
        c01 = fmaf(t0, p1[k], c01);
        c11 = fmaf(t1, p1[k], c11);
    }
    #pragma unroll
    for (int off = 16; off; off >>= 1) {
        c00 += __shfl_down_sync(0xFFFFFFFFu, c00, off);
        c01 += __shfl_down_sync(0xFFFFFFFFu, c01, off);
        c11 += __shfl_down_sync(0xFFFFFFFFu, c11, off);
    }
    int w = tid >> 5;
    if ((tid & 31) == 0) { red0[w] = c00; red1[w] = c01; red2[w] = c11; }
    __syncthreads();
    if (tid == 0) {
        float s0 = 0.f, s1 = 0.f, s2 = 0.f;
        #pragma unroll
        for (int i = 0; i < 8; i++) { s0 += red0[i]; s1 += red1[i]; s2 += red2[i]; }
        float* o = g_a + (size_t)blockIdx.x * 3;
        o[0] = s0; o[1] = s1; o[2] = s2;
    }
}

// ---------------------------------------------------------------------------
// Kernel 3: per-b scan. 128 blocks (one per b), 64 threads (one per t).
// Each thread redundantly runs the recursion up to its own t (no serialization
// across threads). rect & logm via closed-form 2x2 spectral functions:
//   f(H) = c1*H + c0*I,  c1 = (f(l1)-f(l2))/(l1-l2)
// ---------------------------------------------------------------------------
__global__ void scan_kernel(const float* __restrict__ lin_w,
                            const float* __restrict__ lin_b,
                            const float* __restrict__ alpha,
                            float* __restrict__ out) {
    __shared__ float a0[64], a1[64], a2[64];
    __shared__ float lw[51], lb[17];
    int b = blockIdx.x, t = threadIdx.x;

    const float* ab = g_a + ((size_t)b * 64 + t) * 3;
    a0[t] = ab[0]; a1[t] = ab[1]; a2[t] = ab[2];
    if (t < 51) lw[t] = lin_w[t];
    if (t < 17) lb[t] = lin_b[t];
    __syncthreads();

    float s  = 1.f / (1.f + expf(-alpha[0]));
    float os = 1.f - s;

    float h00 = 0.f, h01 = 0.f, h11 = 0.f;
    for (int k = 0; k <= t; k++) {
        // rect(h): clamp eigenvalues at EPSV
        float mean = 0.5f * (h00 + h11);
        float diff = 0.5f * (h00 - h11);
        float rad  = sqrtf(diff * diff + h01 * h01);
        float r00, r01, r11;
        if (rad > 1e-20f) {
            float l1 = mean + rad, l2 = mean - rad;
            float m1 = fmaxf(l1, EPSV), m2 = fmaxf(l2, EPSV);
            float c1 = (m1 - m2) / (l1 - l2);   // exact 1.0 when both above EPS
            float c0 = m1 - c1 * l1;
            r00 = c1 * h00 + c0;
            r01 = c1 * h01;
            r11 = c1 * h11 + c0;
        } else {
            // H ~ mean*I (also covers the h0 = 0 case -> EPS*I)
            if (mean >= EPSV) { r00 = h00; r01 = h01; r11 = h11; }
            else              { r00 = EPSV; r01 = 0.f; r11 = EPSV; }
        }
        h00 = fmaf(s, a0[k], os * r00);
        h01 = fmaf(s, a1[k], os * r01);
        h11 = fmaf(s, a2[k], os * r11);
    }

    // logm(h): eigenvalues strictly positive by construction
    float mean = 0.5f * (h00 + h11);
    float diff = 0.5f * (h00 - h11);
    float rad  = sqrtf(diff * diff + h01 * h01);
    float l1 = mean + rad, l2 = mean - rad;
    float d  = l1 - l2;
    float c1, c0;
    if (d > 0.f) {
        c1 = log1pf(d / l2) / d;        // stable divided difference of log
    } else {
        c1 = 1.f / l1;                  // degenerate: derivative
    }
    c0 = logf(l2) - c1 * l2;
    float v0 = c1 * h00 + c0;
    float v1 = c1 * h01;
    float v2 = c1 * h11 + c0;

    float* o = out + ((size_t)b * 64 + t) * 17;
    #pragma unroll
    for (int j = 0; j < 17; j++)
        o[j] = fmaf(lw[j * 3], v0, fmaf(lw[j * 3 + 1], v1, fmaf(lw[j * 3 + 2], v2, lb[j])));
}

// ---------------------------------------------------------------------------
extern "C" void kernel_launch(void* const* d_in, const int* in_sizes, int n_in,
                              void* d_out, int out_size) {
    const float* x     = (const float*)d_in[0];  // (128,64,57,57)
    const float* W1    = (const float*)d_in[1];  // (57,20)
    const float* W2    = (const float*)d_in[2];  // (20,10)
    const float* W3    = (const float*)d_in[3];  // (10,2)
    const float* lin_w = (const float*)d_in[4];  // (17,3)
    const float* lin_b = (const float*)d_in[5];  // (17,)
    const float* alpha = (const float*)d_in[6];  // (1,)
    float* out = (float*)d_out;                  // (128,64,17)

    compute_P_kernel<<<1, 128>>>(W1, W2, W3);
    stage_a_kernel<<<128 * 64, 256>>>(x);
    scan_kernel<<<128, 64>>>(lin_w, lin_b, alpha, out);
}

// round 2
// speedup vs baseline: 1.1478x; 1.1478x over previous
#include <cuda_runtime.h>
#include <math.h>

#define EPSV 1e-4f
#define NM 3249            // 57*57
#define NLD 13             // ceil(3249/256)

// Scratch (allocation-free): per-(b,t) symmetric 2x2 results + per-b arrival counters.
// __device__ globals are zero-initialized at module load; counters are reset to 0
// by the scanning block each launch, so graph replays stay correct.
__device__ float g_a[128 * 64 * 3];
__device__ int   g_cnt[128];

// ---------------------------------------------------------------------------
// Single fused kernel. grid = 8192 blocks (one per (b,t)), 256 threads.
//  Phase 1: issue all 13 x-loads (MLP=13/warp) BEFORE anything else.
//  Phase 2: redundantly compute P = W1@W2@W3 in shared (hidden under loads).
//  Phase 3: a[bt] = P^T x P (3 reductions), write to g_a, bump counter[b].
//  Phase 4: the last block to finish for b runs the T=64 scan + logm + head.
// ---------------------------------------------------------------------------
__global__ void __launch_bounds__(256)
fused_kernel(const float* __restrict__ x,
             const float* __restrict__ W1,
             const float* __restrict__ W2,
             const float* __restrict__ W3,
             const float* __restrict__ lin_w,
             const float* __restrict__ lin_b,
             const float* __restrict__ alpha,
             float* __restrict__ out) {
    __shared__ float p0[57], p1[57];
    __shared__ float W23[40];
    __shared__ float red0[8], red1[8], red2[8];
    __shared__ int   sh_last;
    __shared__ float a0[64], a1[64], a2[64];
    __shared__ float lw[51], lb[17];

    const int tid = threadIdx.x;
    const int bt  = blockIdx.x;
    const int b   = bt >> 6;
    const float* xm = x + (size_t)bt * NM;

    // --- Phase 1: batched streaming loads (max MLP) ---
    float v[NLD];
    #pragma unroll
    for (int j = 0; j < NLD; j++) {
        int idx = tid + 256 * j;
        v[j] = (idx < NM) ? __ldcs(xm + idx) : 0.f;
    }

    // --- Phase 2: P = W1@W2@W3 in shared (overlapped with loads in flight) ---
    if (tid < 40) {
        int j = tid >> 1, u = tid & 1;
        float s = 0.f;
        #pragma unroll
        for (int k = 0; k < 10; k++) s = fmaf(__ldg(W2 + j * 10 + k), __ldg(W3 + k * 2 + u), s);
        W23[tid] = s;
    }
    __syncthreads();
    if (tid < 114) {
        int i = tid >> 1, u = tid & 1;
        float s = 0.f;
        #pragma unroll
        for (int j = 0; j < 20; j++) s = fmaf(__ldg(W1 + i * 20 + j), W23[j * 2 + u], s);
        if (u == 0) p0[i] = s; else p1[i] = s;
    }
    __syncthreads();

    // --- Phase 3: 3 weighted reductions over the 57x57 matrix ---
    float c00 = 0.f, c01 = 0.f, c11 = 0.f;
    #pragma unroll
    for (int j = 0; j < NLD; j++) {
        int idx = tid + 256 * j;
        idx = (idx < NM) ? idx : (NM - 1);     // v[j]==0 there, weight irrelevant
        int i = idx / 57;
        int k = idx - i * 57;
        float t0 = p0[i] * v[j];
        float t1 = p1[i] * v[j];
        c00 = fmaf(t0, p0[k], c00);
        c01 = fmaf(t0, p1[k], c01);
        c11 = fmaf(t1, p1[k], c11);
    }
    #pragma unroll
    for (int off = 16; off; off >>= 1) {
        c00 += __shfl_down_sync(0xFFFFFFFFu, c00, off);
        c01 += __shfl_down_sync(0xFFFFFFFFu, c01, off);
        c11 += __shfl_down_sync(0xFFFFFFFFu, c11, off);
    }
    int w = tid >> 5;
    if ((tid & 31) == 0) { red0[w] = c00; red1[w] = c01; red2[w] = c11; }
    __syncthreads();
    if (tid == 0) {
        float s0 = 0.f, s1 = 0.f, s2 = 0.f;
        #pragma unroll
        for (int i = 0; i < 8; i++) { s0 += red0[i]; s1 += red1[i]; s2 += red2[i]; }
        float* o = g_a + (size_t)bt * 3;
        o[0] = s0; o[1] = s1; o[2] = s2;
        __threadfence();
        int old = atomicAdd(&g_cnt[b], 1);
        sh_last = (old == 63);
        if (old == 63) g_cnt[b] = 0;           // reset for next graph replay
    }
    __syncthreads();

    if (!sh_last) return;

    // --- Phase 4: scan for this b (last-arriving block only) ---
    __threadfence();                            // acquire side of the counter handshake
    if (tid < 64) {
        const float* ab = g_a + ((size_t)b * 64 + tid) * 3;
        a0[tid] = ab[0]; a1[tid] = ab[1]; a2[tid] = ab[2];
    }
    if (tid < 51) lw[tid] = lin_w[tid];
    if (tid < 17) lb[tid] = lin_b[tid];
    __syncthreads();

    if (tid >= 64) return;
    const int t = tid;
    float s  = 1.f / (1.f + expf(-alpha[0]));
    float os = 1.f - s;

    float h00 = 0.f, h01 = 0.f, h11 = 0.f;
    for (int k = 0; k <= t; k++) {
        float mean = 0.5f * (h00 + h11);
        float diff = 0.5f * (h00 - h11);
        float rad  = sqrtf(diff * diff + h01 * h01);
        float r00, r01, r11;
        if (rad > 1e-20f) {
            float l1 = mean + rad, l2 = mean - rad;
            float m1 = fmaxf(l1, EPSV), m2 = fmaxf(l2, EPSV);
            float c1 = (m1 - m2) / (l1 - l2);   // exactly 1.0 when both above EPS
            float c0 = m1 - c1 * l1;
            r00 = c1 * h00 + c0;
            r01 = c1 * h01;
            r11 = c1 * h11 + c0;
        } else {
            if (mean >= EPSV) { r00 = h00; r01 = h01; r11 = h11; }
            else              { r00 = EPSV; r01 = 0.f; r11 = EPSV; }
        }
        h00 = fmaf(s, a0[k], os * r00);
        h01 = fmaf(s, a1[k], os * r01);
        h11 = fmaf(s, a2[k], os * r11);
    }

    // logm via stable divided difference (eigenvalues > 0 by construction)
    float mean = 0.5f * (h00 + h11);
    float diff = 0.5f * (h00 - h11);
    float rad  = sqrtf(diff * diff + h01 * h01);
    float l1 = mean + rad, l2 = mean - rad;
    float d  = l1 - l2;
    float c1 = (d > 0.f) ? (log1pf(d / l2) / d) : (1.f / l1);
    float c0 = logf(l2) - c1 * l2;
    float v0 = c1 * h00 + c0;
    float v1 = c1 * h01;
    float v2 = c1 * h11 + c0;

    float* o = out + ((size_t)b * 64 + t) * 17;
    #pragma unroll
    for (int j = 0; j < 17; j++)
        o[j] = fmaf(lw[j * 3], v0, fmaf(lw[j * 3 + 1], v1, fmaf(lw[j * 3 + 2], v2, lb[j])));
}

// ---------------------------------------------------------------------------
extern "C" void kernel_launch(void* const* d_in, const int* in_sizes, int n_in,
                              void* d_out, int out_size) {
    const float* x     = (const float*)d_in[0];  // (128,64,57,57)
    const float* W1    = (const float*)d_in[1];  // (57,20)
    const float* W2    = (const float*)d_in[2];  // (20,10)
    const float* W3    = (const float*)d_in[3];  // (10,2)
    const float* lin_w = (const float*)d_in[4];  // (17,3)
    const float* lin_b = (const float*)d_in[5];  // (17,)
    const float* alpha = (const float*)d_in[6];  // (1,)
    float* out = (float*)d_out;                  // (128,64,17)

    fused_kernel<<<128 * 64, 256>>>(x, W1, W2, W3, lin_w, lin_b, alpha, out);
}

// round 3
// speedup vs baseline: 1.4786x; 1.2881x over previous
#include <cuda_runtime.h>
#include <math.h>

#define EPSV 1e-4f
#define NM   3249           // 57*57 floats per matrix
#define GM   4              // matrices per block
#define NQ   3249           // float4 quads per block (GM*NM/4)

// Scratch (allocation-free). Counters zero-init at load; last arriver resets -> replay-safe.
__device__ float g_a[128 * 64 * 3];
__device__ int   g_cnt[128];

// Dynamic shared layout (floats):
#define SM_X_OFF   0        // 12996 floats: 4 staged matrices
#define SM_PQ_OFF  12996    // float2[57] -> floats 12996..13110
#define SM_W23_OFF 13110    // 40 floats
#define SM_RED_OFF 13150    // 8 warps * 3
#define SM_LAST_OFF 13174   // int flag
#define SM_FLOATS  13176
#define SM_BYTES   (SM_FLOATS * 4)

__global__ void __launch_bounds__(256, 4)
fused_kernel(const float* __restrict__ x,
             const float* __restrict__ W1,
             const float* __restrict__ W2,
             const float* __restrict__ W3,
             const float* __restrict__ lin_w,
             const float* __restrict__ lin_b,
             const float* __restrict__ alpha,
             float* __restrict__ out) {
    extern __shared__ float sm[];
    float*  sm_x   = sm + SM_X_OFF;
    float2* sm_pq  = (float2*)(sm + SM_PQ_OFF);
    float*  sm_w23 = sm + SM_W23_OFF;
    float*  sm_red = sm + SM_RED_OFF;
    int*    sm_last = (int*)(sm + SM_LAST_OFF);

    const int tid = threadIdx.x;
    const int blk = blockIdx.x;                 // 2048 blocks, 4 matrices each
    const float4* xq = (const float4*)(x + (size_t)blk * (GM * NM)); // 16B aligned

    // --- Wave 1: 7 vector loads into registers (MLP), all indices < NQ ---
    float4 v[7];
    #pragma unroll
    for (int j = 0; j < 7; j++) v[j] = __ldcs(&xq[tid + 256 * j]);

    // --- P = W1@W2@W3, overlapped with loads in flight ---
    if (tid < 40) {
        int j = tid >> 1, u = tid & 1;
        float s = 0.f;
        #pragma unroll
        for (int k = 0; k < 10; k++) s = fmaf(__ldg(W2 + j * 10 + k), __ldg(W3 + k * 2 + u), s);
        sm_w23[tid] = s;
    }
    __syncthreads();
    if (tid < 114) {
        int i = tid >> 1, u = tid & 1;
        float s = 0.f;
        #pragma unroll
        for (int j = 0; j < 20; j++) s = fmaf(__ldg(W1 + i * 20 + j), sm_w23[j * 2 + u], s);
        ((float*)&sm_pq[i])[u] = s;
    }

    // --- Stage wave 1, then wave 2 (predicated) ---
    #pragma unroll
    for (int j = 0; j < 7; j++)
        *(float4*)(sm_x + 4 * (tid + 256 * j)) = v[j];
    #pragma unroll
    for (int j = 7; j < 13; j++) {
        int q = tid + 256 * j;
        if (q < NQ) {
            float4 t = __ldcs(&xq[q]);
            *(float4*)(sm_x + 4 * q) = t;
        }
    }
    __syncthreads();

    // --- Compute: lane owns a row; k warp-uniform; bank stride 57%32=25 -> conflict-free ---
    const int wid  = tid >> 5, lane = tid & 31;
    const int m    = wid >> 1;                   // matrix 0..3
    const int row  = ((wid & 1) << 5) + lane;    // 0..63, active if <57
    float c00 = 0.f, c01 = 0.f, c11 = 0.f;
    if (row < 57) {
        const float* xr = sm_x + m * NM + row * 57;
        float y0 = 0.f, y1 = 0.f;
        #pragma unroll
        for (int k = 0; k < 57; k++) {
            float  vv = xr[k];
            float2 p  = sm_pq[k];                // uniform broadcast
            y0 = fmaf(vv, p.x, y0);
            y1 = fmaf(vv, p.y, y1);
        }
        float2 pi = sm_pq[row];
        c00 = pi.x * y0;
        c01 = pi.x * y1;
        c11 = pi.y * y1;
    }
    #pragma unroll
    for (int off = 16; off; off >>= 1) {
        c00 += __shfl_down_sync(0xFFFFFFFFu, c00, off);
        c01 += __shfl_down_sync(0xFFFFFFFFu, c01, off);
        c11 += __shfl_down_sync(0xFFFFFFFFu, c11, off);
    }
    if (lane == 0) {
        sm_red[wid * 3 + 0] = c00;
        sm_red[wid * 3 + 1] = c01;
        sm_red[wid * 3 + 2] = c11;
    }
    __syncthreads();

    // --- Combine warp pairs, publish to global, release ---
    if (tid < 4) {
        float s0 = sm_red[(2 * tid) * 3 + 0] + sm_red[(2 * tid + 1) * 3 + 0];
        float s1 = sm_red[(2 * tid) * 3 + 1] + sm_red[(2 * tid + 1) * 3 + 1];
        float s2 = sm_red[(2 * tid) * 3 + 2] + sm_red[(2 * tid + 1) * 3 + 2];
        float* o = g_a + (size_t)(GM * blk + tid) * 3;
        o[0] = s0; o[1] = s1; o[2] = s2;
        __threadfence();
    }
    __syncthreads();

    const int b = blk >> 4;                      // 16 blocks per b
    if (tid == 0) {
        int old = atomicAdd(&g_cnt[b], 1);
        *sm_last = (old == 15);
        if (old == 15) g_cnt[b] = 0;             // reset for graph replay
    }
    __syncthreads();
    if (!*sm_last) return;

    // --- Scan phase (only last-arriving block per b) ---
    __threadfence();                             // acquire
    float* a0 = sm_x;                            // reuse staged region
    float* a1 = sm_x + 64;
    float* a2 = sm_x + 128;
    float* lw = sm_x + 192;                      // 51
    float* lb = sm_x + 243;                      // 17
    if (tid < 64) {
        const float* ab = g_a + ((size_t)b * 64 + tid) * 3;
        a0[tid] = ab[0]; a1[tid] = ab[1]; a2[tid] = ab[2];
    }
    if (tid < 51) lw[tid] = lin_w[tid];
    if (tid < 17) lb[tid] = lin_b[tid];
    __syncthreads();
    if (tid >= 64) return;

    const int t = tid;
    float s  = 1.f / (1.f + expf(-alpha[0]));
    float os = 1.f - s;

    float h00 = 0.f, h01 = 0.f, h11 = 0.f;
    for (int k = 0; k <= t; k++) {
        float mean = 0.5f * (h00 + h11);
        float diff = 0.5f * (h00 - h11);
        float rad  = sqrtf(diff * diff + h01 * h01);
        float r00, r01, r11;
        if (rad > 1e-20f) {
            float l1 = mean + rad, l2 = mean - rad;
            float m1 = fmaxf(l1, EPSV), m2 = fmaxf(l2, EPSV);
            float c1 = (m1 - m2) / (l1 - l2);
            float c0 = m1 - c1 * l1;
            r00 = c1 * h00 + c0;
            r01 = c1 * h01;
            r11 = c1 * h11 + c0;
        } else {
            if (mean >= EPSV) { r00 = h00; r01 = h01; r11 = h11; }
            else              { r00 = EPSV; r01 = 0.f; r11 = EPSV; }
        }
        h00 = fmaf(s, a0[k], os * r00);
        h01 = fmaf(s, a1[k], os * r01);
        h11 = fmaf(s, a2[k], os * r11);
    }

    float mean = 0.5f * (h00 + h11);
    float diff = 0.5f * (h00 - h11);
    float rad  = sqrtf(diff * diff + h01 * h01);
    float l1 = mean + rad, l2 = mean - rad;
    float d  = l1 - l2;
    float c1 = (d > 0.f) ? (log1pf(d / l2) / d) : (1.f / l1);
    float c0 = logf(l2) - c1 * l2;
    float v0 = c1 * h00 + c0;
    float v1 = c1 * h01;
    float v2 = c1 * h11 + c0;

    float* o = out + ((size_t)b * 64 + t) * 17;
    #pragma unroll
    for (int j = 0; j < 17; j++)
        o[j] = fmaf(lw[j * 3], v0, fmaf(lw[j * 3 + 1], v1, fmaf(lw[j * 3 + 2], v2, lb[j])));
}

// ---------------------------------------------------------------------------
extern "C" void kernel_launch(void* const* d_in, const int* in_sizes, int n_in,
                              void* d_out, int out_size) {
    const float* x     = (const float*)d_in[0];  // (128,64,57,57)
    const float* W1    = (const float*)d_in[1];  // (57,20)
    const float* W2    = (const float*)d_in[2];  // (20,10)
    const float* W3    = (const float*)d_in[3];  // (10,2)
    const float* lin_w = (const float*)d_in[4];  // (17,3)
    const float* lin_b = (const float*)d_in[5];  // (17,)
    const float* alpha = (const float*)d_in[6];  // (1,)
    float* out = (float*)d_out;                  // (128,64,17)

    cudaFuncSetAttribute(fused_kernel, cudaFuncAttributeMaxDynamicSharedMemorySize, SM_BYTES);
    fused_kernel<<<2048, 256, SM_BYTES>>>(x, W1, W2, W3, lin_w, lin_b, alpha, out);
}

// round 5
// speedup vs baseline: 1.7078x; 1.1550x over previous
#include <cuda_runtime.h>
#include <cstdint>
#include <math.h>

#define EPSV 1e-4f
#define NM   3249           // 57*57 floats per matrix
#define GM   4              // matrices per block
#define NQ   3249           // float4 quads per block (GM*NM/4)

// Scratch (allocation-free). Counter reset by last arriver -> graph-replay safe.
__device__ float g_a[128 * 64 * 3];
__device__ int   g_cnt[128];

// Shared layout (floats)
#define SM_X_OFF    0        // 12996: 4 staged matrices
#define SM_PQ_OFF   12996    // float2[57] = 114 floats
#define SM_W23_OFF  13110    // 40
#define SM_C_OFF    13150    // 228*3 per-row partials
#define SM_LAST_OFF 13834    // int flag
#define SM_FLOATS   13836
#define SM_BYTES    (SM_FLOATS * 4)

__device__ __forceinline__ void cp_async16(unsigned int saddr, const void* gptr) {
    asm volatile("cp.async.cg.shared.global [%0], [%1], 16;\n" :: "r"(saddr), "l"(gptr));
}

__global__ void __launch_bounds__(512, 4)
fused_kernel(const float* __restrict__ x,
             const float* __restrict__ W1,
             const float* __restrict__ W2,
             const float* __restrict__ W3,
             const float* __restrict__ lin_w,
             const float* __restrict__ lin_b,
             const float* __restrict__ alpha,
             float* __restrict__ out) {
    extern __shared__ float sm[];
    float*  sm_x   = sm + SM_X_OFF;
    float2* sm_pq  = (float2*)(sm + SM_PQ_OFF);
    float*  sm_w23 = sm + SM_W23_OFF;
    float*  sm_c   = sm + SM_C_OFF;
    int*    sm_last = (int*)(sm + SM_LAST_OFF);

    const int tid = threadIdx.x;
    const int blk = blockIdx.x;                 // 2048 blocks, 4 matrices each
    const float4* xq = (const float4*)(x + (size_t)blk * (GM * NM)); // 16B aligned

    unsigned int sx_base;
    asm("{ .reg .u64 t; cvta.to.shared.u64 t, %1; cvt.u32.u64 %0, t; }"
        : "=r"(sx_base) : "l"(sm_x));

    // --- Issue all async copies (no registers for data, max MLP) ---
    #pragma unroll
    for (int j = 0; j < 6; j++) {
        int q = tid + 512 * j;
        cp_async16(sx_base + 16u * q, &xq[q]);
    }
    {
        int q = tid + 512 * 6;
        if (q < NQ) cp_async16(sx_base + 16u * q, &xq[q]);
    }
    asm volatile("cp.async.commit_group;\n" ::: "memory");

    // --- P = W1@W2@W3 (independent of the async copies) ---
    if (tid < 40) {
        int j = tid >> 1, u = tid & 1;
        float s = 0.f;
        #pragma unroll
        for (int k = 0; k < 10; k++) s = fmaf(__ldg(W2 + j * 10 + k), __ldg(W3 + k * 2 + u), s);
        sm_w23[tid] = s;
    }
    __syncthreads();
    if (tid < 114) {
        int i = tid >> 1, u = tid & 1;
        float s = 0.f;
        #pragma unroll
        for (int j = 0; j < 20; j++) s = fmaf(__ldg(W1 + i * 20 + j), sm_w23[j * 2 + u], s);
        ((float*)&sm_pq[i])[u] = s;
    }

    asm volatile("cp.async.wait_group 0;\n" ::: "memory");
    __syncthreads();

    // --- Compute: thread t owns global row t (addr = t*57 + k), bank stride 25 ---
    if (tid < 228) {
        const float* xr = sm_x + tid * 57;
        float y0 = 0.f, y1 = 0.f;
        #pragma unroll
        for (int k = 0; k < 57; k++) {
            float  vv = xr[k];
            float2 p  = sm_pq[k];                // warp-uniform broadcast
            y0 = fmaf(vv, p.x, y0);
            y1 = fmaf(vv, p.y, y1);
        }
        int m = tid / 57;
        float2 pi = sm_pq[tid - 57 * m];
        sm_c[tid * 3 + 0] = pi.x * y0;
        sm_c[tid * 3 + 1] = pi.x * y1;
        sm_c[tid * 3 + 2] = pi.y * y1;
    }
    __syncthreads();

    // --- Finalize: 12 threads each sum 57 partials for (matrix m, component c) ---
    if (tid < 12) {
        int m = tid / 3;
        int comp = tid - 3 * m;
        const float* base = sm_c + (m * 57) * 3 + comp;
        float s = 0.f;
        #pragma unroll
        for (int r = 0; r < 57; r++) s += base[r * 3];
        g_a[(size_t)(GM * blk + m) * 3 + comp] = s;
    }
    __threadfence();
    __syncthreads();

    const int b = blk >> 4;                      // 16 blocks per b
    if (tid == 0) {
        int old = atomicAdd(&g_cnt[b], 1);
        *sm_last = (old == 15);
        if (old == 15) g_cnt[b] = 0;             // reset for graph replay
    }
    __syncthreads();
    if (!*sm_last) return;

    // --- Scan phase (only last-arriving block per b) ---
    __threadfence();                             // acquire
    float* a0 = sm_x;                            // reuse staged region
    float* a1 = sm_x + 64;
    float* a2 = sm_x + 128;
    float* lw = sm_x + 192;                      // 51
    float* lb = sm_x + 243;                      // 17
    if (tid < 64) {
        const float* ab = g_a + ((size_t)b * 64 + tid) * 3;
        a0[tid] = ab[0]; a1[tid] = ab[1]; a2[tid] = ab[2];
    }
    if (tid < 51) lw[tid] = lin_w[tid];
    if (tid < 17) lb[tid] = lin_b[tid];
    __syncthreads();
    if (tid >= 64) return;

    const int t = tid;
    float s  = 1.f / (1.f + expf(-alpha[0]));
    float os = 1.f - s;

    float h00 = 0.f, h01 = 0.f, h11 = 0.f;
    for (int k = 0; k <= t; k++) {
        float mean = 0.5f * (h00 + h11);
        float diff = 0.5f * (h00 - h11);
        float rad  = sqrtf(diff * diff + h01 * h01);
        float r00, r01, r11;
        if (rad > 1e-20f) {
            float l1 = mean + rad, l2 = mean - rad;
            float m1 = fmaxf(l1, EPSV), m2 = fmaxf(l2, EPSV);
            float c1 = (m1 - m2) / (l1 - l2);
            float c0 = m1 - c1 * l1;
            r00 = c1 * h00 + c0;
            r01 = c1 * h01;
            r11 = c1 * h11 + c0;
        } else {
            if (mean >= EPSV) { r00 = h00; r01 = h01; r11 = h11; }
            else              { r00 = EPSV; r01 = 0.f; r11 = EPSV; }
        }
        h00 = fmaf(s, a0[k], os * r00);
        h01 = fmaf(s, a1[k], os * r01);
        h11 = fmaf(s, a2[k], os * r11);
    }

    float mean = 0.5f * (h00 + h11);
    float diff = 0.5f * (h00 - h11);
    float rad  = sqrtf(diff * diff + h01 * h01);
    float l1 = mean + rad, l2 = mean - rad;
    float d  = l1 - l2;
    float c1 = (d > 0.f) ? (log1pf(d / l2) / d) : (1.f / l1);
    float c0 = logf(l2) - c1 * l2;
    float v0 = c1 * h00 + c0;
    float v1 = c1 * h01;
    float v2 = c1 * h11 + c0;

    float* o = out + ((size_t)b * 64 + t) * 17;
    #pragma unroll
    for (int j = 0; j < 17; j++)
        o[j] = fmaf(lw[j * 3], v0, fmaf(lw[j * 3 + 1], v1, fmaf(lw[j * 3 + 2], v2, lb[j])));
}

// ---------------------------------------------------------------------------
extern "C" void kernel_launch(void* const* d_in, const int* in_sizes, int n_in,
                              void* d_out, int out_size) {
    const float* x     = (const float*)d_in[0];  // (128,64,57,57)
    const float* W1    = (const float*)d_in[1];  // (57,20)
    const float* W2    = (const float*)d_in[2];  // (20,10)
    const float* W3    = (const float*)d_in[3];  // (10,2)
    const float* lin_w = (const float*)d_in[4];  // (17,3)
    const float* lin_b = (const float*)d_in[5];  // (17,)
    const float* alpha = (const float*)d_in[6];  // (1,)
    float* out = (float*)d_out;                  // (128,64,17)

    cudaFuncSetAttribute(fused_kernel, cudaFuncAttributeMaxDynamicSharedMemorySize, SM_BYTES);
    fused_kernel<<<2048, 512, SM_BYTES>>>(x, W1, W2, W3, lin_w, lin_b, alpha, out);
}